// round 5
// baseline (speedup 1.0000x reference)
#include <cuda_runtime.h>
#include <cstddef>
#include <cstdint>

namespace {

constexpr int B = 2, N = 512, C = 64, H = 8;
constexpr int THREADS = 512;           // one thread per n-row
constexpr int SCH    = 16;             // channels per stage
constexpr int STAGES = 8;              // 4 q-stages + 4 k-stages
constexpr int RSTR   = 20;             // buf row stride in floats (16 + 4 pad)
constexpr int BUF_FLOATS = 512 * RSTR; // one buffer (40 KB)
// dynamic smem: Ws[1024] | buf0 | buf1 | wsum[16*8]
constexpr size_t SMEM_BYTES = (1024 + 2 * BUF_FLOATS + 16 * H) * sizeof(float);

#define FMA2(acc, a, b) \
    asm("fma.rn.f32x2 %0, %1, %2, %0;" : "+l"(acc) : "l"(a), "l"(b))

__device__ __forceinline__ unsigned long long pack2(float lo, float hi) {
    unsigned long long d;
    asm("mov.b64 %0, {%1, %2};" : "=l"(d) : "r"(__float_as_uint(lo)), "r"(__float_as_uint(hi)));
    return d;
}
__device__ __forceinline__ void unpack2(unsigned long long v, float& lo, float& hi) {
    unsigned int l, h;
    asm("mov.b64 {%0, %1}, %2;" : "=r"(l), "=r"(h) : "l"(v));
    lo = __uint_as_float(l);
    hi = __uint_as_float(h);
}
__device__ __forceinline__ uint32_t smem_u32(const void* p) {
    return (uint32_t)__cvta_generic_to_shared(p);
}
__device__ __forceinline__ void cp_async16(uint32_t dst, const void* src) {
    asm volatile("cp.async.cg.shared.global [%0], [%1], 16;" :: "r"(dst), "l"(src));
}

__global__ __launch_bounds__(THREADS, 2)
void mha_fused_kernel(const float* __restrict__ q,
                      const float* __restrict__ k,
                      const float* __restrict__ roi,
                      const float* __restrict__ W,
                      const float* __restrict__ bias,
                      float* __restrict__ out)
{
    extern __shared__ float smem[];
    float* Ws   = smem;                         // [c][h], 4 KB
    float* bufs = smem + 1024;                  // 2 x BUF_FLOATS
    float* wsum = smem + 1024 + 2 * BUF_FLOATS; // [16][H]

    const int tid  = threadIdx.x;
    const int bm   = blockIdx.x;                // b*N + m
    const int warp = tid >> 5;
    const int lane = tid & 31;

    const float* qb = q   + (size_t)bm * N * C;
    const float* kb = k   + (size_t)bm * N * C;

    // W[h][128] -> Ws[c][h]
    for (int i = tid; i < 128 * H; i += THREADS) {
        const int h = i >> 7, c = i & 127;
        Ws[c * H + h] = W[i];
    }

    // ---- stage issue: 16 channels for all 512 rows, 4 cp.async per thread ----
    auto issue_stage = [&](int s) {
        const float* src = (s < 4 ? qb + s * SCH : kb + (s - 4) * SCH);
        float* dst = bufs + (s & 1) * BUF_FLOATS;
#pragma unroll
        for (int i = 0; i < 4; ++i) {
            const int idx = i * THREADS + tid;   // 0..2047 float4 slots
            const int row = idx >> 2, c4 = idx & 3;
            cp_async16(smem_u32(&dst[row * RSTR + c4 * 4]), src + (size_t)row * C + c4 * 4);
        }
        asm volatile("cp.async.commit_group;" ::: "memory");
    };

    issue_stage(0);

    unsigned long long acc[4];
    acc[0] = pack2(bias[0], bias[1]);
    acc[1] = pack2(bias[2], bias[3]);
    acc[2] = pack2(bias[4], bias[5]);
    acc[3] = pack2(bias[6], bias[7]);

#pragma unroll
    for (int s = 0; s < STAGES; ++s) {
        asm volatile("cp.async.wait_group 0;" ::: "memory");
        __syncthreads();                          // stage s visible; stage s-1 readers done
        if (s + 1 < STAGES) issue_stage(s + 1);   // overlaps with compute below

        const float* r0 = bufs + (s & 1) * BUF_FLOATS + tid * RSTR;

        float4 d[4];
#pragma unroll
        for (int j = 0; j < 4; ++j) d[j] = reinterpret_cast<const float4*>(r0)[j];

        const ulonglong2* wp = reinterpret_cast<const ulonglong2*>(&Ws[(s * SCH) * H]);
#pragma unroll
        for (int j = 0; j < 4; ++j) {
            const float vv[4] = {d[j].x, d[j].y, d[j].z, d[j].w};
#pragma unroll
            for (int cc = 0; cc < 4; ++cc) {
                const int c = j * 4 + cc;
                const ulonglong2 w01 = wp[c * 2];       // heads 0-3
                const ulonglong2 w45 = wp[c * 2 + 1];   // heads 4-7
                const unsigned long long a2 = pack2(vv[cc], vv[cc]);
                FMA2(acc[0], a2, w01.x);
                FMA2(acc[1], a2, w01.y);
                FMA2(acc[2], a2, w45.x);
                FMA2(acc[3], a2, w45.y);
            }
        }
    }

    // ---- epilogue: exp * roi for this thread's row ----
    float e[H], sums[H];
    {
        float av[H];
#pragma unroll
        for (int j = 0; j < 4; ++j) unpack2(acc[j], av[2 * j], av[2 * j + 1]);
        const float r = roi[(size_t)bm * N + tid];
#pragma unroll
        for (int h = 0; h < H; ++h) {
            e[h] = __expf(av[h]) * r;
            sums[h] = e[h];
        }
    }

    // ---- block-wide row-sum over 512 n (16 warps) ----
#pragma unroll
    for (int h = 0; h < H; ++h) {
        float s = sums[h];
#pragma unroll
        for (int off = 16; off > 0; off >>= 1)
            s += __shfl_xor_sync(0xffffffffu, s, off);
        sums[h] = s;
    }
    if (lane == 0) {
#pragma unroll
        for (int h = 0; h < H; ++h) wsum[warp * H + h] = sums[h];
    }
    __syncthreads();

    float inv[H];
#pragma unroll
    for (int h = 0; h < H; ++h) {
        float t = 0.f;
#pragma unroll
        for (int w = 0; w < 16; ++w) t += wsum[w * H + h];
        inv[h] = 1.0f / t;
    }

    // ---- normalize + coalesced store (2x STG.128) ----
    {
        float* op = out + ((size_t)bm * N + tid) * H;
        float4 a, b2;
        a.x  = e[0] * inv[0];  a.y  = e[1] * inv[1];
        a.z  = e[2] * inv[2];  a.w  = e[3] * inv[3];
        b2.x = e[4] * inv[4];  b2.y = e[5] * inv[5];
        b2.z = e[6] * inv[6];  b2.w = e[7] * inv[7];
        *reinterpret_cast<float4*>(op)     = a;
        *reinterpret_cast<float4*>(op + 4) = b2;
    }
}

} // namespace

extern "C" void kernel_launch(void* const* d_in, const int* in_sizes, int n_in,
                              void* d_out, int out_size)
{
    const float* q    = (const float*)d_in[0];
    const float* k    = (const float*)d_in[1];
    const float* roi  = (const float*)d_in[2];
    const float* W    = (const float*)d_in[3];
    const float* bias = (const float*)d_in[4];
    float* out        = (float*)d_out;

    (void)in_sizes; (void)n_in; (void)out_size;

    cudaFuncSetAttribute(mha_fused_kernel,
                         cudaFuncAttributeMaxDynamicSharedMemorySize,
                         (int)SMEM_BYTES);

    dim3 grid(B * N);     // one block per (b, m) row
    dim3 block(THREADS);
    mha_fused_kernel<<<grid, block, SMEM_BYTES>>>(q, k, roi, W, bias, out);
}